// round 2
// baseline (speedup 1.0000x reference)
#include <cuda_runtime.h>
#include <cstdint>
#include <math.h>

#define HH 64
#define WW 64
#define NPIX 4096
#define NA 9
#define NANCH 36864
#define NSORT 65536
#define KPRE 2000
#define KPOST 256
#define NCLS 21
#define NO 105
#define NOP 112
#define KDIM 50176
#define KSPLIT 32
#define KRANGE 1568

// output layout (flat concat, tuple order)
#define OUT_CLS0 0
#define OUT_TFM0 73728
#define OUT_PROP 221184
#define OUT_FBOX 222464
#define OUT_FCLS 223744
#define OUT_FTFM 229120

// ---------------- scratch (static device globals; no allocation) ----------
__device__ float g_h[256 * NPIX];                       // conv output (4 MB)
__device__ float g_bx[NANCH], g_by[NANCH], g_bw[NANCH], g_bh[NANCH];
__device__ unsigned long long g_key[NSORT];
__device__ float g_tx[KPRE], g_ty[KPRE], g_tw[KPRE], g_th[KPRE];
__device__ float g_rois[KPOST * 4];
__device__ float g_feats[KPOST * KDIM];                 // 51 MB
__device__ float g_wT[KDIM * NOP];                      // 22.5 MB
__device__ float g_part[KSPLIT * NOP * KPOST];          // 3.7 MB
__device__ float g_ho[KPOST * NO];

// ---------------- K1: 3x3 conv + bias --------------------------------------
__global__ void k_conv3x3(const float* __restrict__ x,
                          const float* __restrict__ w,
                          const float* __restrict__ bias) {
    __shared__ float xs[16][10][19];
    __shared__ float ws[16][9][32];
    int tid = threadIdx.x;
    int pg = tid & 31, og = tid >> 5;
    int row = pg >> 2, col0 = (pg & 3) * 4;
    int ocl = og * 4;
    int bx0 = blockIdx.x * 16, by0 = blockIdx.y * 8, oc0 = blockIdx.z * 32;
    float acc[4][4] = {};
    for (int ic0 = 0; ic0 < 256; ic0 += 16) {
        for (int t = tid; t < 16 * 10 * 18; t += 256) {
            int ii = t / 180, rr = (t / 18) % 10, cc = t % 18;
            int gy = by0 + rr - 1, gx = bx0 + cc - 1;
            float v = 0.f;
            if (gy >= 0 && gy < HH && gx >= 0 && gx < WW)
                v = x[(ic0 + ii) * NPIX + gy * WW + gx];
            xs[ii][rr][cc] = v;
        }
        for (int t = tid; t < 16 * 9 * 32; t += 256) {
            int o = t & 31, k = (t >> 5) % 9, ii = t / 288;
            ws[ii][k][o] = w[(oc0 + o) * 2304 + (ic0 + ii) * 9 + k];
        }
        __syncthreads();
        for (int ii = 0; ii < 16; ii++) {
#pragma unroll
            for (int ky = 0; ky < 3; ky++)
#pragma unroll
                for (int kx = 0; kx < 3; kx++) {
                    float x0v = xs[ii][row + ky][col0 + kx + 0];
                    float x1v = xs[ii][row + ky][col0 + kx + 1];
                    float x2v = xs[ii][row + ky][col0 + kx + 2];
                    float x3v = xs[ii][row + ky][col0 + kx + 3];
                    float w0 = ws[ii][ky * 3 + kx][ocl + 0];
                    float w1 = ws[ii][ky * 3 + kx][ocl + 1];
                    float w2 = ws[ii][ky * 3 + kx][ocl + 2];
                    float w3 = ws[ii][ky * 3 + kx][ocl + 3];
                    acc[0][0] += x0v * w0; acc[0][1] += x0v * w1; acc[0][2] += x0v * w2; acc[0][3] += x0v * w3;
                    acc[1][0] += x1v * w0; acc[1][1] += x1v * w1; acc[1][2] += x1v * w2; acc[1][3] += x1v * w3;
                    acc[2][0] += x2v * w0; acc[2][1] += x2v * w1; acc[2][2] += x2v * w2; acc[2][3] += x2v * w3;
                    acc[3][0] += x3v * w0; acc[3][1] += x3v * w1; acc[3][2] += x3v * w2; acc[3][3] += x3v * w3;
                }
        }
        __syncthreads();
    }
#pragma unroll
    for (int p2 = 0; p2 < 4; p2++)
#pragma unroll
        for (int o = 0; o < 4; o++) {
            int oc = oc0 + ocl + o;
            g_h[oc * NPIX + (by0 + row) * WW + bx0 + col0 + p2] = acc[p2][o] + bias[oc];
        }
}

// ---------------- K2: RPN linear heads (54 x 4096) --------------------------
__global__ void k_rpn_heads(const float* __restrict__ cls_w, const float* __restrict__ cls_b,
                            const float* __restrict__ tfm_w, const float* __restrict__ tfm_b,
                            float* __restrict__ out) {
    __shared__ float hs[32][128];
    __shared__ float wsm[32][54];
    int tid = threadIdx.x;
    int lane = tid & 127, half = tid >> 7;
    int p0 = blockIdx.x * 128;
    float acc[27];
#pragma unroll
    for (int q = 0; q < 27; q++) acc[q] = 0.f;
    for (int c0 = 0; c0 < 256; c0 += 32) {
        for (int t = tid; t < 32 * 128; t += 256) {
            int c = t >> 7, pl = t & 127;
            hs[c][pl] = g_h[(c0 + c) * NPIX + p0 + pl];
        }
        for (int t = tid; t < 32 * 54; t += 256) {
            int c = t / 54, o = t % 54;
            wsm[c][o] = (o < 18) ? cls_w[o * 256 + c0 + c] : tfm_w[(o - 18) * 256 + c0 + c];
        }
        __syncthreads();
        for (int c = 0; c < 32; c++) {
            float hv = hs[c][lane];
#pragma unroll
            for (int q = 0; q < 27; q++) acc[q] += hv * wsm[c][half * 27 + q];
        }
        __syncthreads();
    }
    int p = p0 + lane;
#pragma unroll
    for (int q = 0; q < 27; q++) {
        int o = half * 27 + q;
        float v = acc[q] + ((o < 18) ? cls_b[o] : tfm_b[o - 18]);
        if (o < 18) out[OUT_CLS0 + o * NPIX + p] = v;
        else        out[OUT_TFM0 + (o - 18) * NPIX + p] = v;
    }
}

// ---------------- K3: score + box decode, sort keys -------------------------
__global__ void k_decode(const float* __restrict__ out, const float* __restrict__ anchors) {
    int gid = blockIdx.x * 256 + threadIdx.x;
    if (gid >= NANCH) {
        if (gid < NSORT) g_key[gid] = 0xFFFFFFFFFFFFFFFFull;
        return;
    }
    int a = gid >> 12;
    int p = gid & 4095;
    int i = p >> 6, j = p & 63;
    float logit = out[OUT_CLS0 + (2 * a) * NPIX + p] - out[OUT_CLS0 + (2 * a + 1) * NPIX + p];
    float obj = 1.0f / (1.0f + expf(-logit));
    float t0 = out[OUT_TFM0 + (4 * a + 0) * NPIX + p];
    float t1 = out[OUT_TFM0 + (4 * a + 1) * NPIX + p];
    float t2 = out[OUT_TFM0 + (4 * a + 2) * NPIX + p];
    float t3 = out[OUT_TFM0 + (4 * a + 3) * NPIX + p];
    float ah = anchors[a * 2 + 0], aw = anchors[a * 2 + 1];
    float bx = (float)j + aw * (t1 - 0.5f) / 16.0f;
    float by = (float)i + ah * (t0 - 0.5f) / 16.0f;
    float bw = aw / 16.0f * expf(t3);
    float bh = ah / 16.0f * expf(t2);
    bx = fminf(fmaxf(bx, 0.f), 63.f);
    by = fminf(fmaxf(by, 0.f), 63.f);
    bw = fminf(fmaxf(bx + bw, 0.f), 63.f) - bx;
    bh = fminf(fmaxf(by + bh, 0.f), 63.f) - by;
    g_bx[gid] = bx; g_by[gid] = by; g_bw[gid] = bw; g_bh[gid] = bh;
    unsigned int sb = __float_as_uint(obj);
    g_key[gid] = ((unsigned long long)(~sb) << 32) | (unsigned int)gid;
}

// ---------------- bitonic sort (ascending keys = descending scores) ---------
__global__ void k_bitonic_local() {
    __shared__ unsigned long long s[4096];
    int base = blockIdx.x * 4096;
    for (int t = threadIdx.x; t < 4096; t += 1024) s[t] = g_key[base + t];
    for (int k = 2; k <= 4096; k <<= 1) {
        for (int j = k >> 1; j > 0; j >>= 1) {
            __syncthreads();
            for (int t = threadIdx.x; t < 2048; t += 1024) {
                int i = ((t & ~(j - 1)) << 1) | (t & (j - 1));
                int l = i | j;
                bool asc = (((base + i) & k) == 0);
                unsigned long long a = s[i], b = s[l];
                bool sw = asc ? (a > b) : (a < b);
                if (sw) { s[i] = b; s[l] = a; }
            }
        }
    }
    __syncthreads();
    for (int t = threadIdx.x; t < 4096; t += 1024) g_key[base + t] = s[t];
}

__global__ void k_bitonic_global(int j, int k) {
    int t = blockIdx.x * 256 + threadIdx.x;  // 32768 workers
    int i = ((t & ~(j - 1)) << 1) | (t & (j - 1));
    int l = i | j;
    bool asc = ((i & k) == 0);
    unsigned long long a = g_key[i], b = g_key[l];
    bool sw = asc ? (a > b) : (a < b);
    if (sw) { g_key[i] = b; g_key[l] = a; }
}

__global__ void k_bitonic_merge(int k) {
    __shared__ unsigned long long s[4096];
    int base = blockIdx.x * 4096;
    for (int t = threadIdx.x; t < 4096; t += 1024) s[t] = g_key[base + t];
    bool asc = ((base & k) == 0);
    for (int j = 2048; j > 0; j >>= 1) {
        __syncthreads();
        for (int t = threadIdx.x; t < 2048; t += 1024) {
            int i = ((t & ~(j - 1)) << 1) | (t & (j - 1));
            int l = i | j;
            unsigned long long a = s[i], b = s[l];
            bool sw = asc ? (a > b) : (a < b);
            if (sw) { s[i] = b; s[l] = a; }
        }
    }
    __syncthreads();
    for (int t = threadIdx.x; t < 4096; t += 1024) g_key[base + t] = s[t];
}

// ---------------- K5: gather top-2000 boxes ---------------------------------
__global__ void k_gather_top() {
    int i = blockIdx.x * 256 + threadIdx.x;
    if (i >= KPRE) return;
    unsigned int idx = (unsigned int)(g_key[i] & 0xFFFFFFFFull);
    g_tx[i] = g_bx[idx];
    g_ty[i] = g_by[idx];
    g_tw[i] = g_bw[idx];
    g_th[i] = g_bh[idx];
}

// ---------------- K6: greedy NMS + select 256 + proposal boxes --------------
__global__ void k_nms_select(float* __restrict__ out) {
    __shared__ float x1s[KPRE], y1s[KPRE], x2s[KPRE], y2s[KPRE], ars[KPRE];
    __shared__ unsigned char keepS[KPRE];
    __shared__ int selS[KPOST];
    int tid = threadIdx.x;
    for (int i = tid; i < KPRE; i += 1024) {
        float x1 = g_tx[i], y1 = g_ty[i], w = g_tw[i], h = g_th[i];
        x1s[i] = x1; y1s[i] = y1; x2s[i] = x1 + w; y2s[i] = y1 + h;
        ars[i] = w * h; keepS[i] = 1;
    }
    for (int i = 0; i < KPRE; i++) {
        __syncthreads();
        if (!keepS[i]) continue;
        float xi1 = x1s[i], yi1 = y1s[i], xi2 = x2s[i], yi2 = y2s[i], ai = ars[i];
        for (int j = i + 1 + tid; j < KPRE; j += 1024) {
            float ix = fmaxf(xi1, x1s[j]);
            float iy = fmaxf(yi1, y1s[j]);
            float iw = fmaxf(fminf(xi2, x2s[j]) - ix, 0.f);
            float ih = fmaxf(fminf(yi2, y2s[j]) - iy, 0.f);
            float inter = iw * ih;
            float iou = inter / (ai + ars[j] - inter);
            if (iou > 0.7f) keepS[j] = 0;
        }
    }
    __syncthreads();
    if (tid == 0) {
        int c = 0;
        for (int i = 0; i < KPRE && c < KPOST; i++) if (keepS[i]) selS[c++] = i;
        for (int i = 0; i < KPRE && c < KPOST; i++) if (!keepS[i]) selS[c++] = i;
    }
    __syncthreads();
    if (tid < KPOST) {
        int r = selS[tid];
        float rx = x1s[r], ry = y1s[r], rw = g_tw[r], rh = g_th[r];
        g_rois[tid * 4 + 0] = rx;
        g_rois[tid * 4 + 1] = ry;
        g_rois[tid * 4 + 2] = rw;
        g_rois[tid * 4 + 3] = rh;
        out[OUT_PROP + tid * 5 + 0] = 0.f;
        out[OUT_PROP + tid * 5 + 1] = rx * 16.f;
        out[OUT_PROP + tid * 5 + 2] = ry * 16.f;
        out[OUT_PROP + tid * 5 + 3] = rw * 16.f;
        out[OUT_PROP + tid * 5 + 4] = rh * 16.f;
    }
}

// ---------------- K7: ROI align (28x28 bilinear -> 14x14 max pool) ----------
__global__ void k_roi_align(const float* __restrict__ x) {
    __shared__ int x0s[28], y0s[28];
    __shared__ float wxs[28], wys[28];
    int roi = blockIdx.x, cg = blockIdx.y, tid = threadIdx.x;
    float rx = g_rois[roi * 4 + 0], ry = g_rois[roi * 4 + 1];
    float rw = g_rois[roi * 4 + 2], rh = g_rois[roi * 4 + 3];
    if (tid < 28) {
        float gx = rx + (((float)tid + 0.5f) * rw) / 28.0f;
        gx = fminf(fmaxf(gx, 0.f), 63.f);
        int x0 = (int)floorf(gx);
        x0 = min(max(x0, 0), 62);
        x0s[tid] = x0; wxs[tid] = gx - (float)x0;
    } else if (tid >= 32 && tid < 60) {
        int g = tid - 32;
        float gy = ry + (((float)g + 0.5f) * rh) / 28.0f;
        gy = fminf(fmaxf(gy, 0.f), 63.f);
        int y0 = (int)floorf(gy);
        y0 = min(max(y0, 0), 62);
        y0s[g] = y0; wys[g] = gy - (float)y0;
    }
    __syncthreads();
    for (int idx = tid; idx < 32 * 196; idx += 256) {
        int cl = idx / 196, pp = idx % 196, pi = pp / 14, pj = pp % 14;
        const float* base = x + (cg * 32 + cl) * NPIX;
        float m = -1e30f;
#pragma unroll
        for (int dy = 0; dy < 2; dy++) {
            int gi = 2 * pi + dy;
            int y0 = y0s[gi]; float wy = wys[gi];
#pragma unroll
            for (int dx = 0; dx < 2; dx++) {
                int gj = 2 * pj + dx;
                int x0 = x0s[gj]; float wx = wxs[gj];
                const float* p00 = base + y0 * WW + x0;
                float f00 = p00[0], f10 = p00[1], f01 = p00[WW], f11 = p00[WW + 1];
                float v = f00 * (1.f - wy) * (1.f - wx) + f01 * wy * (1.f - wx)
                        + f10 * (1.f - wy) * wx + f11 * wy * wx;
                m = fmaxf(m, v);
            }
        }
        g_feats[roi * KDIM + (cg * 32 + cl) * 196 + pp] = m;
    }
}

// ---------------- K8: transpose head_w to k-major ---------------------------
__global__ void k_transposeW(const float* __restrict__ hw) {
    __shared__ float tile[32][33];
    int k0 = blockIdx.x * 32, o0 = blockIdx.y * 32;
    int tx = threadIdx.x, ty = threadIdx.y;
    for (int r = ty; r < 32; r += 8) {
        int o = o0 + r;
        tile[r][tx] = (o < NO) ? hw[o * KDIM + k0 + tx] : 0.f;
    }
    __syncthreads();
    for (int r = ty; r < 32; r += 8) {
        int o = o0 + tx;
        if (o < NOP) g_wT[(k0 + r) * NOP + o] = tile[tx][r];
    }
}

// ---------------- K9: head GEMM (256x105x50176, split-K) --------------------
__global__ void k_head_gemm() {
    __shared__ float wsm[16][NOP];
    __shared__ float fsm[16][64];
    int tid = threadIdx.x;
    int mt = blockIdx.x, kz = blockIdx.y;
    int ng = tid & 15, mg = tid >> 4;
    int o0 = ng * 7;
    int r0 = mt * 64 + mg * 4;
    int K0 = kz * KRANGE;
    float acc[7][4] = {};
    for (int kc = 0; kc < KRANGE; kc += 16) {
        for (int t = tid; t < 16 * NOP; t += 256) {
            int kk = t / NOP, o = t % NOP;
            wsm[kk][o] = g_wT[(K0 + kc + kk) * NOP + o];
        }
        {
            int r = tid >> 2;
            int kk4 = (tid & 3) * 4;
            const float4 f4 = *(const float4*)(g_feats + (mt * 64 + r) * KDIM + K0 + kc + kk4);
            fsm[kk4 + 0][r] = f4.x; fsm[kk4 + 1][r] = f4.y;
            fsm[kk4 + 2][r] = f4.z; fsm[kk4 + 3][r] = f4.w;
        }
        __syncthreads();
#pragma unroll
        for (int kk = 0; kk < 16; kk++) {
            float wv[7], fv[4];
#pragma unroll
            for (int q = 0; q < 7; q++) wv[q] = wsm[kk][o0 + q];
#pragma unroll
            for (int s = 0; s < 4; s++) fv[s] = fsm[kk][mg * 4 + s];
#pragma unroll
            for (int q = 0; q < 7; q++)
#pragma unroll
                for (int s = 0; s < 4; s++) acc[q][s] += wv[q] * fv[s];
        }
        __syncthreads();
    }
#pragma unroll
    for (int q = 0; q < 7; q++)
#pragma unroll
        for (int s = 0; s < 4; s++)
            g_part[kz * NOP * KPOST + (o0 + q) * KPOST + r0 + s] = acc[q][s];
}

// ---------------- K10: reduce split-K + bias, emit cls/tfm ------------------
__global__ void k_head_reduce(const float* __restrict__ head_b, float* __restrict__ out) {
    int o = blockIdx.x;
    int roi = threadIdx.x;
    if (o >= NO) return;
    float s = 0.f;
    for (int z = 0; z < KSPLIT; z++) s += g_part[z * NOP * KPOST + o * KPOST + roi];
    s += head_b[o];
    g_ho[roi * NO + o] = s;
    if (o < NCLS) out[OUT_FCLS + roi * NCLS + o] = s;
    else          out[OUT_FTFM + roi * 84 + (o - NCLS)] = s;
}

// ---------------- K11: final box decode ------------------------------------
__global__ void k_finalize(float* __restrict__ out) {
    int roi = threadIdx.x;
    const float* ho = g_ho + roi * NO;
    int det = 0;
    float best = ho[0];
    for (int c = 1; c < NCLS; c++) {
        float v = ho[c];
        if (v > best) { best = v; det = c; }
    }
    float t0 = ho[NCLS + det * 4 + 0];
    float t1 = ho[NCLS + det * 4 + 1];
    float t2 = ho[NCLS + det * 4 + 2];
    float t3 = ho[NCLS + det * 4 + 3];
    float X = g_rois[roi * 4 + 0] * 16.f;
    float Y = g_rois[roi * 4 + 1] * 16.f;
    float Wd = g_rois[roi * 4 + 2] * 16.f;
    float Hd = g_rois[roi * 4 + 3] * 16.f;
    out[OUT_FBOX + roi * 5 + 0] = 0.f;
    out[OUT_FBOX + roi * 5 + 1] = X + Wd * t1;
    out[OUT_FBOX + roi * 5 + 2] = Y + Hd * t0;
    out[OUT_FBOX + roi * 5 + 3] = Wd * expf(t3);
    out[OUT_FBOX + roi * 5 + 4] = Hd * expf(t2);
}

// ---------------- launcher --------------------------------------------------
extern "C" void kernel_launch(void* const* d_in, const int* in_sizes, int n_in,
                              void* d_out, int out_size) {
    const float* x      = (const float*)d_in[0];
    const float* rpn_w  = (const float*)d_in[1];
    const float* rpn_b  = (const float*)d_in[2];
    const float* cls_w  = (const float*)d_in[3];
    const float* cls_b  = (const float*)d_in[4];
    const float* tfm_w  = (const float*)d_in[5];
    const float* tfm_b  = (const float*)d_in[6];
    const float* head_w = (const float*)d_in[7];
    const float* head_b = (const float*)d_in[8];
    const float* anchors = (const float*)d_in[9];
    float* out = (float*)d_out;

    k_conv3x3<<<dim3(4, 8, 8), 256>>>(x, rpn_w, rpn_b);
    k_rpn_heads<<<32, 256>>>(cls_w, cls_b, tfm_w, tfm_b, out);
    k_decode<<<256, 256>>>(out, anchors);

    k_bitonic_local<<<16, 1024>>>();
    for (int k = 8192; k <= 65536; k <<= 1) {
        for (int j = k >> 1; j >= 4096; j >>= 1)
            k_bitonic_global<<<128, 256>>>(j, k);
        k_bitonic_merge<<<16, 1024>>>(k);
    }

    k_gather_top<<<8, 256>>>();
    k_nms_select<<<1, 1024>>>(out);

    k_transposeW<<<dim3(KDIM / 32, 4), dim3(32, 8)>>>(head_w);
    k_roi_align<<<dim3(KPOST, 8), 256>>>(x);
    k_head_gemm<<<dim3(4, KSPLIT), 256>>>();
    k_head_reduce<<<NOP, 256>>>(head_b, out);
    k_finalize<<<1, 256>>>(out);
}

// round 3
// speedup vs baseline: 2.0975x; 2.0975x over previous
#include <cuda_runtime.h>
#include <cstdint>
#include <math.h>

#define HH 64
#define WW 64
#define NPIX 4096
#define NA 9
#define NANCH 36864
#define NSORT 65536
#define KPRE 2000
#define KPOST 256
#define NCLS 21
#define NO 105
#define NOP 112
#define KDIM 50176
#define KSPLIT 64
#define KRANGE 784

// output layout (flat concat, tuple order)
#define OUT_CLS0 0
#define OUT_TFM0 73728
#define OUT_PROP 221184
#define OUT_FBOX 222464
#define OUT_FCLS 223744
#define OUT_FTFM 229120

typedef unsigned int u32;
typedef unsigned long long u64;

// ---------------- scratch (static device globals; no allocation) ----------
__device__ float g_h[256 * NPIX];                       // conv output (4 MB)
__device__ float g_bx[NANCH], g_by[NANCH], g_bw[NANCH], g_bh[NANCH];
__device__ u64 g_key[NSORT];
__device__ u64 g_key2[16384];
__device__ float g_tx[KPRE], g_ty[KPRE], g_tw[KPRE], g_th[KPRE];
__device__ u32 g_mask[2048 * 64];                       // NMS suppression bitmask
__device__ float g_rois[KPOST * 4];
__device__ float g_feats[KPOST * KDIM];                 // 51 MB
__device__ float g_wT[KDIM * NOP];                      // 22.5 MB
__device__ float g_part[KSPLIT * NOP * KPOST];          // 7.3 MB
__device__ float g_ho[KPOST * NO];

// ---------------- K1: 3x3 conv + bias (128 thr, 4px x 8oc per thread) ------
__global__ void k_conv3x3(const float* __restrict__ x,
                          const float* __restrict__ w,
                          const float* __restrict__ bias) {
    __shared__ float xs[16][10][19];
    __shared__ float ws[16][9][32];
    int tid = threadIdx.x;               // 0..127
    int pg = tid & 31, og = tid >> 5;    // og 0..3 (one warp each)
    int row = pg >> 2, col0 = (pg & 3) * 4;
    int ocl = og * 8;
    int bx0 = blockIdx.x * 16, by0 = blockIdx.y * 8, oc0 = blockIdx.z * 32;
    float acc[8][4] = {};
    for (int ic0 = 0; ic0 < 256; ic0 += 16) {
        for (int t = tid; t < 2880; t += 128) {
            int ii = t / 180, rr = (t / 18) % 10, cc = t % 18;
            int gy = by0 + rr - 1, gx = bx0 + cc - 1;
            float v = 0.f;
            if (gy >= 0 && gy < HH && gx >= 0 && gx < WW)
                v = x[(ic0 + ii) * NPIX + gy * WW + gx];
            xs[ii][rr][cc] = v;
        }
        for (int t = tid; t < 4608; t += 128) {
            int o = t & 31, k = (t >> 5) % 9, ii = t / 288;
            ws[ii][k][o] = w[(oc0 + o) * 2304 + (ic0 + ii) * 9 + k];
        }
        __syncthreads();
        for (int ii = 0; ii < 16; ii++) {
#pragma unroll
            for (int ky = 0; ky < 3; ky++)
#pragma unroll
                for (int kx = 0; kx < 3; kx++) {
                    float x0 = xs[ii][row + ky][col0 + kx + 0];
                    float x1 = xs[ii][row + ky][col0 + kx + 1];
                    float x2 = xs[ii][row + ky][col0 + kx + 2];
                    float x3 = xs[ii][row + ky][col0 + kx + 3];
#pragma unroll
                    for (int o = 0; o < 8; o++) {
                        float wv = ws[ii][ky * 3 + kx][ocl + o];
                        acc[o][0] += x0 * wv;
                        acc[o][1] += x1 * wv;
                        acc[o][2] += x2 * wv;
                        acc[o][3] += x3 * wv;
                    }
                }
        }
        __syncthreads();
    }
    int py = by0 + row, px = bx0 + col0;
#pragma unroll
    for (int o = 0; o < 8; o++) {
        int oc = oc0 + ocl + o;
        float b = bias[oc];
        float4 v;
        v.x = acc[o][0] + b; v.y = acc[o][1] + b;
        v.z = acc[o][2] + b; v.w = acc[o][3] + b;
        *(float4*)&g_h[oc * NPIX + py * WW + px] = v;
    }
}

// ---------------- K2: RPN linear heads (54 x 4096) --------------------------
__global__ void k_rpn_heads(const float* __restrict__ cls_w, const float* __restrict__ cls_b,
                            const float* __restrict__ tfm_w, const float* __restrict__ tfm_b,
                            float* __restrict__ out) {
    __shared__ float hs[32][128];
    __shared__ float wsm[32][54];
    int tid = threadIdx.x;
    int lane = tid & 127, half = tid >> 7;
    int p0 = blockIdx.x * 128;
    float acc[27];
#pragma unroll
    for (int q = 0; q < 27; q++) acc[q] = 0.f;
    for (int c0 = 0; c0 < 256; c0 += 32) {
        for (int t = tid; t < 32 * 128; t += 256) {
            int c = t >> 7, pl = t & 127;
            hs[c][pl] = g_h[(c0 + c) * NPIX + p0 + pl];
        }
        for (int t = tid; t < 32 * 54; t += 256) {
            int c = t / 54, o = t % 54;
            wsm[c][o] = (o < 18) ? cls_w[o * 256 + c0 + c] : tfm_w[(o - 18) * 256 + c0 + c];
        }
        __syncthreads();
        for (int c = 0; c < 32; c++) {
            float hv = hs[c][lane];
#pragma unroll
            for (int q = 0; q < 27; q++) acc[q] += hv * wsm[c][half * 27 + q];
        }
        __syncthreads();
    }
    int p = p0 + lane;
#pragma unroll
    for (int q = 0; q < 27; q++) {
        int o = half * 27 + q;
        float v = acc[q] + ((o < 18) ? cls_b[o] : tfm_b[o - 18]);
        if (o < 18) out[OUT_CLS0 + o * NPIX + p] = v;
        else        out[OUT_TFM0 + (o - 18) * NPIX + p] = v;
    }
}

// ---------------- K3: score + box decode, sort keys -------------------------
__global__ void k_decode(const float* __restrict__ out, const float* __restrict__ anchors) {
    int gid = blockIdx.x * 256 + threadIdx.x;
    if (gid >= NANCH) {
        if (gid < NSORT) g_key[gid] = 0xFFFFFFFFFFFFFFFFull;
        return;
    }
    int a = gid >> 12;
    int p = gid & 4095;
    int i = p >> 6, j = p & 63;
    float logit = out[OUT_CLS0 + (2 * a) * NPIX + p] - out[OUT_CLS0 + (2 * a + 1) * NPIX + p];
    float obj = 1.0f / (1.0f + expf(-logit));
    float t0 = out[OUT_TFM0 + (4 * a + 0) * NPIX + p];
    float t1 = out[OUT_TFM0 + (4 * a + 1) * NPIX + p];
    float t2 = out[OUT_TFM0 + (4 * a + 2) * NPIX + p];
    float t3 = out[OUT_TFM0 + (4 * a + 3) * NPIX + p];
    float ah = anchors[a * 2 + 0], aw = anchors[a * 2 + 1];
    float bx = (float)j + aw * (t1 - 0.5f) / 16.0f;
    float by = (float)i + ah * (t0 - 0.5f) / 16.0f;
    float bw = aw / 16.0f * expf(t3);
    float bh = ah / 16.0f * expf(t2);
    bx = fminf(fmaxf(bx, 0.f), 63.f);
    by = fminf(fmaxf(by, 0.f), 63.f);
    bw = fminf(fmaxf(bx + bw, 0.f), 63.f) - bx;
    bh = fminf(fmaxf(by + bh, 0.f), 63.f) - by;
    g_bx[gid] = bx; g_by[gid] = by; g_bw[gid] = bw; g_bh[gid] = bh;
    unsigned int sb = __float_as_uint(obj);
    g_key[gid] = ((u64)(~sb) << 32) | (unsigned int)gid;
}

// ---------------- local bitonic sort: each 4096-block fully ASCENDING -------
__global__ void k_bitonic_local() {
    __shared__ u64 s[4096];
    int base = blockIdx.x * 4096;
    for (int t = threadIdx.x; t < 4096; t += 1024) s[t] = g_key[base + t];
    for (int k = 2; k <= 4096; k <<= 1) {
        for (int j = k >> 1; j > 0; j >>= 1) {
            __syncthreads();
            for (int t = threadIdx.x; t < 2048; t += 1024) {
                int i = ((t & ~(j - 1)) << 1) | (t & (j - 1));
                int l = i | j;
                bool asc = ((i & k) == 0);
                u64 a = s[i], b = s[l];
                bool sw = asc ? (a > b) : (a < b);
                if (sw) { s[i] = b; s[l] = a; }
            }
        }
    }
    __syncthreads();
    for (int t = threadIdx.x; t < 4096; t += 1024) g_key[base + t] = s[t];
}

// ---------------- top-2048 pairwise merge (half-cleaner + bitonic merge) ----
__global__ void k_topmerge(int round) {
    __shared__ u64 s[2048];
    const u64* in; u64* outp; int stride;
    if (round == 1)      { in = g_key;  outp = g_key2; stride = 4096; }
    else if (round == 2) { in = g_key2; outp = g_key;  stride = 2048; }
    else if (round == 3) { in = g_key;  outp = g_key2; stride = 2048; }
    else                 { in = g_key2; outp = g_key;  stride = 2048; }
    int b = blockIdx.x;
    const u64* A = in + (size_t)b * 2 * stride;
    const u64* Bp = A + stride;
    for (int t = threadIdx.x; t < 2048; t += 1024) {
        u64 a = A[t], bb = Bp[2047 - t];
        s[t] = a < bb ? a : bb;      // smallest 2048 of union, bitonic
    }
    for (int j = 1024; j > 0; j >>= 1) {
        __syncthreads();
        int t = threadIdx.x;
        int i = ((t & ~(j - 1)) << 1) | (t & (j - 1));
        int l = i | j;
        u64 a = s[i], bq = s[l];
        if (a > bq) { s[i] = bq; s[l] = a; }
    }
    __syncthreads();
    for (int t = threadIdx.x; t < 2048; t += 1024) outp[b * 2048 + t] = s[t];
}

// ---------------- gather top-2000 boxes ------------------------------------
__global__ void k_gather_top() {
    int i = blockIdx.x * 256 + threadIdx.x;
    if (i >= KPRE) return;
    unsigned int idx = (unsigned int)(g_key[i] & 0xFFFFFFFFull);
    g_tx[i] = g_bx[idx];
    g_ty[i] = g_by[idx];
    g_tw[i] = g_bw[idx];
    g_th[i] = g_bh[idx];
}

// ---------------- NMS stage 1: IOU suppression bitmask ----------------------
__global__ void k_iou_build() {
    __shared__ float sx1[KPRE], sy1[KPRE], sx2[KPRE], sy2[KPRE], sar[KPRE];
    int tid = threadIdx.x;
    for (int t = tid; t < KPRE; t += 512) {
        float x1 = g_tx[t], y1 = g_ty[t], w = g_tw[t], h = g_th[t];
        sx1[t] = x1; sy1[t] = y1; sx2[t] = x1 + w; sy2[t] = y1 + h; sar[t] = w * h;
    }
    __syncthreads();
    int i = blockIdx.x * 16 + (tid >> 5);
    int lane = tid & 31;
    if (i >= KPRE) return;
    float x1 = sx1[i], y1 = sy1[i], x2 = sx2[i], y2 = sy2[i], ar = sar[i];
    for (int wq = 0; wq < 63; wq++) {
        u32 bits = 0;
        if ((wq + 1) * 32 > i + 1) {        // word has some j > i (warp-uniform)
            int j = wq * 32 + lane;
            bool sup = false;
            if (j < KPRE && j > i) {
                float ix = fmaxf(x1, sx1[j]);
                float iy = fmaxf(y1, sy1[j]);
                float iw = fmaxf(fminf(x2, sx2[j]) - ix, 0.f);
                float ih = fmaxf(fminf(y2, sy2[j]) - iy, 0.f);
                float inter = iw * ih;
                float iou = inter / (ar + sar[j] - inter);
                sup = iou > 0.7f;
            }
            bits = __ballot_sync(0xffffffffu, sup);
        }
        if (lane == 0) g_mask[i * 64 + wq] = bits;
    }
    if (lane == 0) g_mask[i * 64 + 63] = 0u;
}

// ---------------- NMS stage 2: serial greedy scan + select 256 --------------
__global__ void k_nms_scan(float* __restrict__ out) {
    __shared__ u32 buf[2][64][64];       // double-buffered mask chunks (32 KB)
    __shared__ u32 keepS[64];
    __shared__ int wpfx[65];
    __shared__ int selS[KPOST];
    int tid = threadIdx.x;
    int lane = tid & 31;
    u32 k0 = 0, k1 = 0;
    if (tid < 32) {
        k0 = 0xFFFFFFFFu;
        k1 = (lane < 30) ? 0xFFFFFFFFu : (lane == 30 ? 0xFFFFu : 0u);   // 2000 bits
    }
    for (int idx = tid; idx < 4096; idx += 1024)
        buf[0][idx >> 6][idx & 63] = g_mask[idx];
    __syncthreads();
    for (int c = 0; c < 32; c++) {
        int cb = c & 1;
        if (tid < 32) {
            int rmax = 2000 - c * 64; if (rmax > 64) rmax = 64;
            for (int r = 0; r < rmax; r++) {
                int i = c * 64 + r;
                int w = i >> 5;
                u32 a0 = __shfl_sync(0xffffffffu, k0, w & 31);
                u32 a1 = __shfl_sync(0xffffffffu, k1, w & 31);
                u32 wv = (w < 32) ? a0 : a1;
                if ((wv >> (i & 31)) & 1u) {
                    k0 &= ~buf[cb][r][lane];
                    k1 &= ~buf[cb][r][32 + lane];
                }
            }
        } else if (c < 31) {
            int t2 = tid - 32;
            int base = (c + 1) * 4096;
            for (int idx = t2; idx < 4096; idx += 992)
                buf[cb ^ 1][idx >> 6][idx & 63] = g_mask[base + idx];
        }
        __syncthreads();
    }
    if (tid < 32) { keepS[lane] = k0; keepS[32 + lane] = k1; }
    __syncthreads();
    if (tid == 0) {
        int s = 0;
        for (int w = 0; w < 64; w++) { wpfx[w] = s; s += __popc(keepS[w]); }
        wpfx[64] = s;
    }
    __syncthreads();
    int tot = wpfx[64];
    for (int t = tid; t < KPRE; t += 1024) {
        u32 wv = keepS[t >> 5];
        int sub = t & 31;
        bool alive = (wv >> sub) & 1u;
        int rank = wpfx[t >> 5] + __popc(wv & ((1u << sub) - 1u));
        if (alive) {
            if (rank < KPOST) selS[rank] = t;
        } else {
            int slot = tot + (t - rank);
            if (slot < KPOST) selS[slot] = t;
        }
    }
    __syncthreads();
    if (tid < KPOST) {
        int r = selS[tid];
        float rx = g_tx[r], ry = g_ty[r], rw = g_tw[r], rh = g_th[r];
        g_rois[tid * 4 + 0] = rx;
        g_rois[tid * 4 + 1] = ry;
        g_rois[tid * 4 + 2] = rw;
        g_rois[tid * 4 + 3] = rh;
        out[OUT_PROP + tid * 5 + 0] = 0.f;
        out[OUT_PROP + tid * 5 + 1] = rx * 16.f;
        out[OUT_PROP + tid * 5 + 2] = ry * 16.f;
        out[OUT_PROP + tid * 5 + 3] = rw * 16.f;
        out[OUT_PROP + tid * 5 + 4] = rh * 16.f;
    }
}

// ---------------- ROI align (28x28 bilinear -> 14x14 max pool) --------------
__global__ void k_roi_align(const float* __restrict__ x) {
    __shared__ int x0s[28], y0s[28];
    __shared__ float wxs[28], wys[28];
    int roi = blockIdx.x, cg = blockIdx.y, tid = threadIdx.x;
    float rx = g_rois[roi * 4 + 0], ry = g_rois[roi * 4 + 1];
    float rw = g_rois[roi * 4 + 2], rh = g_rois[roi * 4 + 3];
    if (tid < 28) {
        float gx = rx + (((float)tid + 0.5f) * rw) / 28.0f;
        gx = fminf(fmaxf(gx, 0.f), 63.f);
        int x0 = (int)floorf(gx);
        x0 = min(max(x0, 0), 62);
        x0s[tid] = x0; wxs[tid] = gx - (float)x0;
    } else if (tid >= 32 && tid < 60) {
        int g = tid - 32;
        float gy = ry + (((float)g + 0.5f) * rh) / 28.0f;
        gy = fminf(fmaxf(gy, 0.f), 63.f);
        int y0 = (int)floorf(gy);
        y0 = min(max(y0, 0), 62);
        y0s[g] = y0; wys[g] = gy - (float)y0;
    }
    __syncthreads();
    for (int idx = tid; idx < 32 * 196; idx += 256) {
        int cl = idx / 196, pp = idx % 196, pi = pp / 14, pj = pp % 14;
        const float* base = x + (cg * 32 + cl) * NPIX;
        float m = -1e30f;
#pragma unroll
        for (int dy = 0; dy < 2; dy++) {
            int gi = 2 * pi + dy;
            int y0 = y0s[gi]; float wy = wys[gi];
#pragma unroll
            for (int dx = 0; dx < 2; dx++) {
                int gj = 2 * pj + dx;
                int x0 = x0s[gj]; float wx = wxs[gj];
                const float* p00 = base + y0 * WW + x0;
                float f00 = p00[0], f10 = p00[1], f01 = p00[WW], f11 = p00[WW + 1];
                float v = f00 * (1.f - wy) * (1.f - wx) + f01 * wy * (1.f - wx)
                        + f10 * (1.f - wy) * wx + f11 * wy * wx;
                m = fmaxf(m, v);
            }
        }
        g_feats[roi * KDIM + (cg * 32 + cl) * 196 + pp] = m;
    }
}

// ---------------- transpose head_w to k-major -------------------------------
__global__ void k_transposeW(const float* __restrict__ hw) {
    __shared__ float tile[32][33];
    int k0 = blockIdx.x * 32, o0 = blockIdx.y * 32;
    int tx = threadIdx.x, ty = threadIdx.y;
    for (int r = ty; r < 32; r += 8) {
        int o = o0 + r;
        tile[r][tx] = (o < NO) ? hw[o * KDIM + k0 + tx] : 0.f;
    }
    __syncthreads();
    for (int r = ty; r < 32; r += 8) {
        int o = o0 + tx;
        if (o < NOP) g_wT[(k0 + r) * NOP + o] = tile[tx][r];
    }
}

// ---------------- head GEMM (256x105x50176, split-K=64) ---------------------
__global__ void k_head_gemm() {
    __shared__ float wsm[16][NOP];
    __shared__ float fsm[16][64];
    int tid = threadIdx.x;
    int mt = blockIdx.x, kz = blockIdx.y;
    int ng = tid & 15, mg = tid >> 4;
    int o0 = ng * 7;
    int r0 = mt * 64 + mg * 4;
    int K0 = kz * KRANGE;
    float acc[7][4] = {};
    for (int kc = 0; kc < KRANGE; kc += 16) {
        for (int t = tid; t < 16 * NOP; t += 256) {
            int kk = t / NOP, o = t % NOP;
            wsm[kk][o] = g_wT[(K0 + kc + kk) * NOP + o];
        }
        {
            int r = tid >> 2;
            int kk4 = (tid & 3) * 4;
            const float4 f4 = *(const float4*)(g_feats + (mt * 64 + r) * KDIM + K0 + kc + kk4);
            fsm[kk4 + 0][r] = f4.x; fsm[kk4 + 1][r] = f4.y;
            fsm[kk4 + 2][r] = f4.z; fsm[kk4 + 3][r] = f4.w;
        }
        __syncthreads();
#pragma unroll
        for (int kk = 0; kk < 16; kk++) {
            float wv[7], fv[4];
#pragma unroll
            for (int q = 0; q < 7; q++) wv[q] = wsm[kk][o0 + q];
#pragma unroll
            for (int s = 0; s < 4; s++) fv[s] = fsm[kk][mg * 4 + s];
#pragma unroll
            for (int q = 0; q < 7; q++)
#pragma unroll
                for (int s = 0; s < 4; s++) acc[q][s] += wv[q] * fv[s];
        }
        __syncthreads();
    }
#pragma unroll
    for (int q = 0; q < 7; q++)
#pragma unroll
        for (int s = 0; s < 4; s++)
            g_part[kz * NOP * KPOST + (o0 + q) * KPOST + r0 + s] = acc[q][s];
}

// ---------------- reduce split-K + bias, emit cls/tfm -----------------------
__global__ void k_head_reduce(const float* __restrict__ head_b, float* __restrict__ out) {
    int o = blockIdx.x;
    int roi = threadIdx.x;
    if (o >= NO) return;
    float s = 0.f;
    for (int z = 0; z < KSPLIT; z++) s += g_part[z * NOP * KPOST + o * KPOST + roi];
    s += head_b[o];
    g_ho[roi * NO + o] = s;
    if (o < NCLS) out[OUT_FCLS + roi * NCLS + o] = s;
    else          out[OUT_FTFM + roi * 84 + (o - NCLS)] = s;
}

// ---------------- final box decode ------------------------------------------
__global__ void k_finalize(float* __restrict__ out) {
    int roi = threadIdx.x;
    const float* ho = g_ho + roi * NO;
    int det = 0;
    float best = ho[0];
    for (int c = 1; c < NCLS; c++) {
        float v = ho[c];
        if (v > best) { best = v; det = c; }
    }
    float t0 = ho[NCLS + det * 4 + 0];
    float t1 = ho[NCLS + det * 4 + 1];
    float t2 = ho[NCLS + det * 4 + 2];
    float t3 = ho[NCLS + det * 4 + 3];
    float X = g_rois[roi * 4 + 0] * 16.f;
    float Y = g_rois[roi * 4 + 1] * 16.f;
    float Wd = g_rois[roi * 4 + 2] * 16.f;
    float Hd = g_rois[roi * 4 + 3] * 16.f;
    out[OUT_FBOX + roi * 5 + 0] = 0.f;
    out[OUT_FBOX + roi * 5 + 1] = X + Wd * t1;
    out[OUT_FBOX + roi * 5 + 2] = Y + Hd * t0;
    out[OUT_FBOX + roi * 5 + 3] = Wd * expf(t3);
    out[OUT_FBOX + roi * 5 + 4] = Hd * expf(t2);
}

// ---------------- launcher --------------------------------------------------
extern "C" void kernel_launch(void* const* d_in, const int* in_sizes, int n_in,
                              void* d_out, int out_size) {
    const float* x      = (const float*)d_in[0];
    const float* rpn_w  = (const float*)d_in[1];
    const float* rpn_b  = (const float*)d_in[2];
    const float* cls_w  = (const float*)d_in[3];
    const float* cls_b  = (const float*)d_in[4];
    const float* tfm_w  = (const float*)d_in[5];
    const float* tfm_b  = (const float*)d_in[6];
    const float* head_w = (const float*)d_in[7];
    const float* head_b = (const float*)d_in[8];
    const float* anchors = (const float*)d_in[9];
    float* out = (float*)d_out;

    k_conv3x3<<<dim3(4, 8, 8), 128>>>(x, rpn_w, rpn_b);
    k_rpn_heads<<<32, 256>>>(cls_w, cls_b, tfm_w, tfm_b, out);
    k_decode<<<256, 256>>>(out, anchors);

    k_bitonic_local<<<16, 1024>>>();
    k_topmerge<<<8, 1024>>>(1);
    k_topmerge<<<4, 1024>>>(2);
    k_topmerge<<<2, 1024>>>(3);
    k_topmerge<<<1, 1024>>>(4);

    k_gather_top<<<8, 256>>>();
    k_iou_build<<<125, 512>>>();
    k_nms_scan<<<1, 1024>>>(out);

    k_transposeW<<<dim3(KDIM / 32, 4), dim3(32, 8)>>>(head_w);
    k_roi_align<<<dim3(KPOST, 8), 256>>>(x);
    k_head_gemm<<<dim3(4, KSPLIT), 256>>>();
    k_head_reduce<<<NOP, 256>>>(head_b, out);
    k_finalize<<<1, 256>>>(out);
}